// round 8
// baseline (speedup 1.0000x reference)
#include <cuda_runtime.h>

typedef unsigned long long u64;

__device__ __forceinline__ u64 pack2(float lo, float hi) {
    u64 r; asm("mov.b64 %0,{%1,%2};" : "=l"(r) : "f"(lo), "f"(hi)); return r;
}
__device__ __forceinline__ void unpack2(u64 v, float& lo, float& hi) {
    asm("mov.b64 {%0,%1}, %2;" : "=f"(lo), "=f"(hi) : "l"(v));
}
__device__ __forceinline__ u64 fma2(u64 a, u64 b, u64 c) {
    u64 d; asm("fma.rn.f32x2 %0,%1,%2,%3;" : "=l"(d) : "l"(a), "l"(b), "l"(c)); return d;
}
__device__ __forceinline__ u64 add2(u64 a, u64 b) {
    u64 d; asm("add.rn.f32x2 %0,%1,%2;" : "=l"(d) : "l"(a), "l"(b)); return d;
}
__device__ __forceinline__ u64 mul2(u64 a, u64 b) {
    u64 d; asm("mul.rn.f32x2 %0,%1,%2;" : "=l"(d) : "l"(a), "l"(b)); return d;
}
__device__ __forceinline__ float sqrt_approx(float x) {
    float r; asm("sqrt.approx.f32 %0, %1;" : "=f"(r) : "f"(x)); return r;
}
// relu both halves of a packed f32x2
__device__ __forceinline__ u64 relu2(u64 v) {
    float lo, hi; unpack2(v, lo, hi);
    return pack2(fmaxf(lo, 0.f), fmaxf(hi, 0.f));
}

constexpr int NE = 7;      // entities
constexpr int DE = 4;      // dims per entity
constexpr int H  = 128;    // half embedding
constexpr int NPAIR = 21;  // unordered pairs
constexpr int OUTC = 2 * H;
constexpr int ROW = NE * OUTC;   // floats per batch element in out

__global__ __launch_bounds__(256, 4)
void enc_kernel(const float* __restrict__ ctx,
                const float* __restrict__ w_prop, const float* __restrict__ b_prop,
                const float* __restrict__ w_rel,  const float* __restrict__ b_rel,
                float* __restrict__ out, int B)
{
    constexpr int PI[NPAIR] = {0,0,0,0,0,0,1,1,1,1,1,2,2,2,2,3,3,3,4,4,5};
    constexpr int PJ[NPAIR] = {1,2,3,4,5,6,2,3,4,5,6,3,4,5,6,4,5,6,5,6,6};

    // four independent 64-thread sub-blocks per CTA, each owns ONE batch.
    // entity values and distances stored BROADCAST-packed (v,v) so the
    // compute stage can feed them straight into fma.rn.f32x2.
    __shared__ __align__(16) u64 sh_ents[4][NE * DE];   // (v,v) per scalar
    __shared__ __align__(16) u64 sh_dist[4][NPAIR];     // (dist,dist)

    const int tid = threadIdx.x;
    const int s   = tid >> 6;        // sub-block 0..3 (one batch each)
    const int t   = tid & 63;        // lane within sub-block
    const int h0  = t * 2;           // this thread's h pair {h0, h0+1}

    const int b = blockIdx.x * 4 + s;     // batch owned by this sub-block

    // ---- stage 1: load 28 entity scalars, broadcast-pack into shared ----
    if (t < NE * DE) {
        float v = ctx[t * B + b];
        sh_ents[s][t] = pack2(v, v);
    }

    // weights/biases as natural float2 over {h0, h0+1} — overlaps stage-1 latency
    u64 wp2[DE], wr2[DE + 1], bp2, br2;
    #pragma unroll
    for (int d = 0; d < DE; d++)     { float2 w = *(const float2*)(w_prop + d * H + h0); wp2[d] = pack2(w.x, w.y); }
    #pragma unroll
    for (int d = 0; d < DE + 1; d++) { float2 w = *(const float2*)(w_rel  + d * H + h0); wr2[d] = pack2(w.x, w.y); }
    { float2 v = *(const float2*)(b_prop + h0); bp2 = pack2(v.x, v.y); }
    { float2 v = *(const float2*)(b_rel  + h0); br2 = pack2(v.x, v.y); }
    const u64 neg1 = pack2(-1.f, -1.f);

    asm volatile("bar.sync %0, 64;" :: "r"(s + 1) : "memory");

    // ---- stage 2: pair distances over first 2 coords, broadcast-packed ----
    if (t < NPAIR) {
        const int i = PI[t], j = PJ[t];
        const float* ef = (const float*)sh_ents[s];   // read lo copy
        float dx = ef[(i*DE+0)*2] - ef[(j*DE+0)*2];
        float dy = ef[(i*DE+1)*2] - ef[(j*DE+1)*2];
        float dist = sqrt_approx(dx*dx + dy*dy);
        sh_dist[s][t] = pack2(dist, dist);
    }
    asm volatile("bar.sync %0, 64;" :: "r"(s + 1) : "memory");

    // ---- stage 3: packed-f32x2 compute, {h0,h0+1} per thread, STG.64 out ----
    float* outp = out + (size_t)b * ROW;

    // per-entity: property embedding AND rel projection q_e = e . w_rel[0:4]
    u64 qd[NE];
    const ulonglong2* e4 = (const ulonglong2*)sh_ents[s];
    #pragma unroll
    for (int e = 0; e < NE; e++) {
        ulonglong2 q0 = e4[e*2 + 0];   // d0, d1 (broadcast-packed)
        ulonglong2 q1 = e4[e*2 + 1];   // d2, d3
        // prop: relu(e . w_prop + b_prop) — stored packed, no unpack
        u64 acc = fma2(q0.x, wp2[0], bp2);
        acc = fma2(q0.y, wp2[1], acc);
        acc = fma2(q1.x, wp2[2], acc);
        acc = fma2(q1.y, wp2[3], acc);
        *(u64*)(outp + e * OUTC + h0) = relu2(acc);
        // q_e = e . w_rel[0:4]  (shared by all pairs touching e)
        u64 q = mul2(q0.x, wr2[0]);
        q = fma2(q0.y, wr2[1], q);
        q = fma2(q1.x, wr2[2], q);
        q = fma2(q1.y, wr2[3], q);
        qd[e] = q;
    }

    // relation embedding: sum_{j != i} relu((q_i - q_j) + dist*w4 + b)
    u64 racc[NE];
    #pragma unroll
    for (int e = 0; e < NE; e++) racc[e] = 0ULL;

    #pragma unroll
    for (int p = 0; p < NPAIR; p++) {
        const int i = PI[p], j = PJ[p];
        u64 sb = fma2(sh_dist[s][p], wr2[4], br2);   // symmetric part
        u64 sd = fma2(qd[j], neg1, qd[i]);           // q_i - q_j
        racc[i] = add2(racc[i], relu2(add2(sb, sd)));        // relu(sb + sd)
        racc[j] = add2(racc[j], relu2(fma2(sd, neg1, sb)));  // relu(sb - sd)
    }

    #pragma unroll
    for (int e = 0; e < NE; e++) {
        *(u64*)(outp + e * OUTC + H + h0) = racc[e];   // STG.64, no unpack
    }
}

extern "C" void kernel_launch(void* const* d_in, const int* in_sizes, int n_in,
                              void* d_out, int out_size) {
    const float* ctx    = (const float*)d_in[0];
    const float* w_prop = (const float*)d_in[1];
    const float* b_prop = (const float*)d_in[2];
    const float* w_rel  = (const float*)d_in[3];
    const float* b_rel  = (const float*)d_in[4];
    float* out = (float*)d_out;

    const int B = in_sizes[0] / (NE * DE);   // 16384
    enc_kernel<<<B / 4, 256>>>(ctx, w_prop, b_prop, w_rel, b_rel, out, B);
}

// round 10
// speedup vs baseline: 1.1356x; 1.1356x over previous
#include <cuda_runtime.h>

typedef unsigned long long u64;

__device__ __forceinline__ u64 pack2(float lo, float hi) {
    u64 r; asm("mov.b64 %0,{%1,%2};" : "=l"(r) : "f"(lo), "f"(hi)); return r;
}
__device__ __forceinline__ void unpack2(u64 v, float& lo, float& hi) {
    asm("mov.b64 {%0,%1}, %2;" : "=f"(lo), "=f"(hi) : "l"(v));
}
__device__ __forceinline__ u64 fma2(u64 a, u64 b, u64 c) {
    u64 d; asm("fma.rn.f32x2 %0,%1,%2,%3;" : "=l"(d) : "l"(a), "l"(b), "l"(c)); return d;
}
__device__ __forceinline__ u64 add2(u64 a, u64 b) {
    u64 d; asm("add.rn.f32x2 %0,%1,%2;" : "=l"(d) : "l"(a), "l"(b)); return d;
}
__device__ __forceinline__ u64 mul2(u64 a, u64 b) {
    u64 d; asm("mul.rn.f32x2 %0,%1,%2;" : "=l"(d) : "l"(a), "l"(b)); return d;
}
__device__ __forceinline__ float sqrt_approx(float x) {
    float r; asm("sqrt.approx.f32 %0, %1;" : "=f"(r) : "f"(x)); return r;
}
// relu both halves of a packed f32x2 (2 scalar FMNMX on register halves)
__device__ __forceinline__ u64 relu2(u64 v) {
    float lo, hi; unpack2(v, lo, hi);
    return pack2(fmaxf(lo, 0.f), fmaxf(hi, 0.f));
}

constexpr int NE = 7;      // entities
constexpr int DE = 4;      // dims per entity
constexpr int H  = 128;    // half embedding
constexpr int NPAIR = 21;  // unordered pairs
constexpr int OUTC = 2 * H;
constexpr int ROW = NE * OUTC;   // floats per batch element in out
constexpr int GRID = 592;        // 148 SMs x 4 resident CTAs = one wave

__global__ __launch_bounds__(256, 4)
void enc_kernel(const float* __restrict__ ctx,
                const float* __restrict__ w_prop, const float* __restrict__ b_prop,
                const float* __restrict__ w_rel,  const float* __restrict__ b_rel,
                float* __restrict__ out, int B, int G)
{
    constexpr int PI[NPAIR] = {0,0,0,0,0,0,1,1,1,1,1,2,2,2,2,3,3,3,4,4,5};
    constexpr int PJ[NPAIR] = {1,2,3,4,5,6,2,3,4,5,6,3,4,5,6,4,5,6,5,6,6};

    // two independent 128-thread sub-blocks per CTA, each owns 2 batches/group
    __shared__ __align__(16) u64 sh_ents[2][NE * DE];   // packed {b0, b0+1}
    __shared__ __align__(16) u64 sh_dist[2][NPAIR];     // packed pair distances

    const int tid = threadIdx.x;
    const int s   = tid >> 7;        // sub-block 0/1
    const int t   = tid & 127;       // lane within sub-block
    const int h   = t;               // one output column per thread
    const int bar = s + 1;           // named barrier id

    // weights broadcast-packed once per CTA (amortized over all groups)
    u64 wp2[DE], wr2[DE + 1], bp2, br2;
    #pragma unroll
    for (int d = 0; d < DE; d++)     { float w = w_prop[d * H + h]; wp2[d] = pack2(w, w); }
    #pragma unroll
    for (int d = 0; d < DE + 1; d++) { float w = w_rel [d * H + h]; wr2[d] = pack2(w, w); }
    { float b = b_prop[h]; bp2 = pack2(b, b); }
    { float b = b_rel [h]; br2 = pack2(b, b); }
    const u64 neg1 = pack2(-1.f, -1.f);

    const bool loader = (t < NE * DE);

    // prefetch first group's ctx pair {b0, b0+1} (LDG.64 matches packed layout)
    int g = blockIdx.x;
    float2 v = make_float2(0.f, 0.f);
    if (loader && g < G) v = *(const float2*)(ctx + t * B + (g * 4 + s * 2));

    for (; g < G; g += GRID) {
        const int b0 = g * 4 + s * 2;

        // ---- stage 1: commit prefetched ctx to shared ----
        if (loader) sh_ents[s][t] = pack2(v.x, v.y);
        asm volatile("bar.sync %0, 128;" :: "r"(bar) : "memory");

        // ---- stage 2: pair distances over first 2 coords ----
        if (t < 2 * NPAIR) {
            const int comp = t >= NPAIR;
            const int p    = comp ? t - NPAIR : t;
            const int i = PI[p], j = PJ[p];
            const float* ef = (const float*)sh_ents[s];
            float dx = ef[(i*DE+0)*2+comp] - ef[(j*DE+0)*2+comp];
            float dy = ef[(i*DE+1)*2+comp] - ef[(j*DE+1)*2+comp];
            ((float*)sh_dist[s])[p * 2 + comp] = sqrt_approx(dx*dx + dy*dy);
        }

        // prefetch next group's ctx — latency covered by stage 3
        const int gn = g + GRID;
        if (loader && gn < G) v = *(const float2*)(ctx + t * B + (gn * 4 + s * 2));

        asm volatile("bar.sync %0, 128;" :: "r"(bar) : "memory");

        // ---- stage 3: packed-f32x2 compute, one h per thread ----
        float* out0 = out + (size_t)b0 * ROW;
        float* out1 = out0 + ROW;     // batch b0+1

        // per-entity: property embedding AND rel projection q_e = e . w_rel[0:4]
        u64 qd[NE];
        const ulonglong2* e4 = (const ulonglong2*)sh_ents[s];
        #pragma unroll
        for (int e = 0; e < NE; e++) {
            ulonglong2 q0 = e4[e*2 + 0];   // d0, d1 (each packed over 2 batches)
            ulonglong2 q1 = e4[e*2 + 1];   // d2, d3
            u64 acc = fma2(q0.x, wp2[0], bp2);
            acc = fma2(q0.y, wp2[1], acc);
            acc = fma2(q1.x, wp2[2], acc);
            acc = fma2(q1.y, wp2[3], acc);
            float lo, hi; unpack2(acc, lo, hi);
            out0[e * OUTC + h] = fmaxf(lo, 0.f);
            out1[e * OUTC + h] = fmaxf(hi, 0.f);
            u64 q = mul2(q0.x, wr2[0]);
            q = fma2(q0.y, wr2[1], q);
            q = fma2(q1.x, wr2[2], q);
            q = fma2(q1.y, wr2[3], q);
            qd[e] = q;
        }

        // relation embedding: sum_{j != i} relu((q_i - q_j) + dist*w4 + b)
        u64 racc[NE];
        #pragma unroll
        for (int e = 0; e < NE; e++) racc[e] = 0ULL;

        #pragma unroll
        for (int p = 0; p < NPAIR; p++) {
            const int i = PI[p], j = PJ[p];
            u64 sb = fma2(sh_dist[s][p], wr2[4], br2);   // symmetric part
            u64 sd = fma2(qd[j], neg1, qd[i]);           // q_i - q_j
            racc[i] = add2(racc[i], relu2(add2(sb, sd)));        // relu(sb + sd)
            racc[j] = add2(racc[j], relu2(fma2(sd, neg1, sb)));  // relu(sb - sd)
        }

        #pragma unroll
        for (int e = 0; e < NE; e++) {
            float lo, hi; unpack2(racc[e], lo, hi);
            out0[e * OUTC + H + h] = lo;
            out1[e * OUTC + H + h] = hi;
        }

        // WAR: stage-3 shared reads complete before next iteration's stage 1
        asm volatile("bar.sync %0, 128;" :: "r"(bar) : "memory");
    }
}

extern "C" void kernel_launch(void* const* d_in, const int* in_sizes, int n_in,
                              void* d_out, int out_size) {
    const float* ctx    = (const float*)d_in[0];
    const float* w_prop = (const float*)d_in[1];
    const float* b_prop = (const float*)d_in[2];
    const float* w_rel  = (const float*)d_in[3];
    const float* b_rel  = (const float*)d_in[4];
    float* out = (float*)d_out;

    const int B = in_sizes[0] / (NE * DE);   // 16384
    const int G = B / 4;                     // 4096 groups of 4 batches
    enc_kernel<<<GRID, 256>>>(ctx, w_prop, b_prop, w_rel, b_rel, out, B, G);
}